// round 9
// baseline (speedup 1.0000x reference)
#include <cuda_runtime.h>
#include <cstdint>

// ---------------------------------------------------------------------------
// MolDecoder: 3-layer GRU autoregressive decoder, B=4096, H=256, V=64, T=120.
// fp32 accurate math; accumulation order = DESCENDING k (fresh rounding draw
// vs rounds 1-6 which all used ascending k and produced a bit-identical
// single argmax flip against the reference).
//   - matvecs: single-accumulator descending-k fp32 FMA chains,
//     i-dot and h-dot separate, biases added separately
//   - tanh: XLA rational (clamp +-9, 4e-4 cutoff), FMA-contracted
//   - sigmoid: 0.5 + 0.5*tanh(0.5x) (contracted)
// Each CTA owns 16 batch elements, h state in SMEM, packed fma.rn.f32x2.
// ---------------------------------------------------------------------------

#define BATCH   4096
#define ZDIM    128
#define HDIM    256
#define VDIM    64
#define TSTEPS  119
#define BTILE   16
#define NPAIR   8                     // BTILE/2 pairs per thread
#define NCTA    (BATCH / BTILE)       // 256
#define NTHR    256
#define HS_STRIDE 18                  // floats per h row (8B aligned, padded)

typedef unsigned long long u64;

// ---- packed f32x2 helpers (lane-wise IEEE fp32 ops) ------------------------
__device__ __forceinline__ u64 pack2(float lo, float hi) {
    u64 r; asm("mov.b64 %0, {%1, %2};" : "=l"(r) : "f"(lo), "f"(hi)); return r;
}
__device__ __forceinline__ u64 pack2dup(float w) {
    u64 r; asm("mov.b64 %0, {%1, %1};" : "=l"(r) : "f"(w)); return r;
}
__device__ __forceinline__ void unpack2(u64 v, float& lo, float& hi) {
    asm("mov.b64 {%0, %1}, %2;" : "=f"(lo), "=f"(hi) : "l"(v));
}
__device__ __forceinline__ u64 fma2(u64 a, u64 b, u64 c) {
    u64 r; asm("fma.rn.f32x2 %0, %1, %2, %3;" : "=l"(r) : "l"(a), "l"(b), "l"(c)); return r;
}
__device__ __forceinline__ u64 add2(u64 a, u64 b) {
    u64 r; asm("add.rn.f32x2 %0, %1, %2;" : "=l"(r) : "l"(a), "l"(b)); return r;
}

// ---- XLA activations, FMA-contracted ---------------------------------------
__device__ __forceinline__ float xla_tanh(float x) {
    float ax = fabsf(x);
    float xc = fminf(fmaxf(x, -9.0f), 9.0f);
    float x2 = __fmul_rn(xc, xc);
    float p = -2.76076847742355e-16f;
    p = __fmaf_rn(p, x2,  2.00018790482477e-13f);
    p = __fmaf_rn(p, x2, -8.60467152213735e-11f);
    p = __fmaf_rn(p, x2,  5.12229709037114e-08f);
    p = __fmaf_rn(p, x2,  1.48572235717979e-05f);
    p = __fmaf_rn(p, x2,  6.37261928875436e-04f);
    p = __fmaf_rn(p, x2,  4.89352455891786e-03f);
    p = __fmul_rn(xc, p);
    float q = 1.19825839466702e-06f;
    q = __fmaf_rn(q, x2, 1.18534705686654e-04f);
    q = __fmaf_rn(q, x2, 2.26843463243900e-03f);
    q = __fmaf_rn(q, x2, 4.89352518554385e-03f);
    float r = __fdiv_rn(p, q);
    return (ax < 0.0004f) ? x : r;
}
__device__ __forceinline__ float xla_sigmoid(float x) {
    float t = xla_tanh(__fmul_rn(0.5f, x));
    return __fmaf_rn(0.5f, t, 0.5f);
}

// ---- persistent device scratch ---------------------------------------------
// 5 matrices packed k4-interleaved: P[m][k4][gj][c] = W[gj][4*k4+c]
__device__ float g_P[5 * 196608];
__device__ float g_G0[64 * 768];            // gi table for layer 0 (incl b_ih0)
__device__ float g_out4[64 * 64 * 4];       // out_w packed [k4][v][c]

// ---------------------------------------------------------------------------
__global__ void prep_kernel(const float* __restrict__ emb,
                            const float* __restrict__ w_ih0,
                            const float* __restrict__ b_ih0,
                            const float* __restrict__ w_hh0,
                            const float* __restrict__ w_ih1,
                            const float* __restrict__ w_hh1,
                            const float* __restrict__ w_ih2,
                            const float* __restrict__ w_hh2,
                            const float* __restrict__ out_w)
{
    int idx = blockIdx.x * 256 + threadIdx.x;
    if (idx < 983040) {                        // pack 5 matrices
        int m = idx / 196608, r = idx % 196608;
        int f4i = r >> 2, c = r & 3;
        int k4 = f4i / 768, gj = f4i % 768;
        const float* src = (m == 0) ? w_hh0 : (m == 1) ? w_ih1 :
                           (m == 2) ? w_hh1 : (m == 3) ? w_ih2 : w_hh2;
        g_P[idx] = src[gj * 256 + 4 * k4 + c];
    } else if (idx < 1032192) {                // G0: fp32 DESCENDING chain + bias
        int i = idx - 983040;
        int v = i / 768, gj = i % 768;
        const float* wrow = w_ih0 + gj * 64;
        const float* e    = emb   + v  * 64;
        float c = 0.0f;
        for (int k = 63; k >= 0; --k) c = __fmaf_rn(wrow[k], e[k], c);
        g_G0[i] = __fadd_rn(c, b_ih0[gj]);
    } else if (idx < 1048576) {                // pack out_w [k4][v][c]
        int i = idx - 1032192;
        int f4i = i >> 2, c = i & 3;
        int k4 = f4i / 64, v = f4i % 64;
        g_out4[i] = out_w[v * 256 + 4 * k4 + c];
    }
}

// ---------------------------------------------------------------------------
// One matrix pass: 3 gates x 8 pairs, DESCENDING k = 255..0, single fp32
// accumulator per (gate, pair).
// ---------------------------------------------------------------------------
__device__ __forceinline__ void accum_phase(const float4* __restrict__ wbase,
                                            const float* __restrict__ xs,
                                            int j, u64* a0, u64* a1, u64* a2)
{
    #pragma unroll 1
    for (int k4 = 63; k4 >= 0; --k4) {
        const float4* wp = wbase + k4 * 768 + j;
        float4 w0 = __ldg(wp);
        float4 w1 = __ldg(wp + 256);
        float4 w2 = __ldg(wp + 512);
        const float* xk = xs + (k4 * 4) * HS_STRIDE;
        float wa0[4] = {w0.x, w0.y, w0.z, w0.w};
        float wa1[4] = {w1.x, w1.y, w1.z, w1.w};
        float wa2[4] = {w2.x, w2.y, w2.z, w2.w};
        #pragma unroll
        for (int c = 3; c >= 0; --c) {
            u64 d0 = pack2dup(wa0[c]);
            u64 d1 = pack2dup(wa1[c]);
            u64 d2 = pack2dup(wa2[c]);
            const float* xr = xk + c * HS_STRIDE;
            #pragma unroll
            for (int p = 0; p < NPAIR; ++p) {
                u64 x2 = *(const u64*)(xr + 2 * p);
                a0[p] = fma2(d0, x2, a0[p]);
                a1[p] = fma2(d1, x2, a1[p]);
                a2[p] = fma2(d2, x2, a2[p]);
            }
        }
    }
}

// GRU epilogue (contracted form):
// r = sigmoid(gi_r + (dh_r + bh_r)) ; u likewise ; hn = dh_n + bh_n
// n = tanh(fma(r, hn, gi_n)) ; h' = fma(1-u, n, u*h)
__device__ __forceinline__ void gru_epilogue(float* hrow,
                                             const u64* gir, const u64* giz, const u64* gin,
                                             const u64* dhr, const u64* dhz, const u64* dhn,
                                             float bhr, float bhz, float bhn)
{
    #pragma unroll
    for (int p = 0; p < NPAIR; ++p) {
        float gr0, gr1, gz0, gz1, gn0, gn1;
        float hr0, hr1, hz0, hz1, hn0, hn1;
        unpack2(gir[p], gr0, gr1);
        unpack2(giz[p], gz0, gz1);
        unpack2(gin[p], gn0, gn1);
        unpack2(dhr[p], hr0, hr1);
        unpack2(dhz[p], hz0, hz1);
        unpack2(dhn[p], hn0, hn1);
        float h0o = hrow[2 * p], h1o = hrow[2 * p + 1];
        float r0 = xla_sigmoid(__fadd_rn(gr0, __fadd_rn(hr0, bhr)));
        float r1 = xla_sigmoid(__fadd_rn(gr1, __fadd_rn(hr1, bhr)));
        float u0 = xla_sigmoid(__fadd_rn(gz0, __fadd_rn(hz0, bhz)));
        float u1 = xla_sigmoid(__fadd_rn(gz1, __fadd_rn(hz1, bhz)));
        float hh0 = __fadd_rn(hn0, bhn), hh1 = __fadd_rn(hn1, bhn);
        float n0 = xla_tanh(__fmaf_rn(r0, hh0, gn0));
        float n1 = xla_tanh(__fmaf_rn(r1, hh1, gn1));
        hrow[2 * p]     = __fmaf_rn(__fsub_rn(1.0f, u0), n0, __fmul_rn(u0, h0o));
        hrow[2 * p + 1] = __fmaf_rn(__fsub_rn(1.0f, u1), n1, __fmul_rn(u1, h1o));
    }
}

// ---------------------------------------------------------------------------
__global__ void __launch_bounds__(NTHR, 1)
decoder_kernel(const float* __restrict__ z,
               const float* __restrict__ z2h_w,
               const float* __restrict__ z2h_b,
               const float* __restrict__ out_b,
               const float* __restrict__ b_hh0,
               const float* __restrict__ b_ih1,
               const float* __restrict__ b_hh1,
               const float* __restrict__ b_ih2,
               const float* __restrict__ b_hh2,
               float* __restrict__ out)
{
    extern __shared__ float sm[];
    float* hs   = sm;                              // [3][256][HS_STRIDE]
    float* uni  = sm + 3 * 256 * HS_STRIDE;        // zs[128][16] / ls[16][65]
    int*   tokS = (int*)(uni + 2048);

    const int tid = threadIdx.x;
    const int j   = tid;
    const int b0  = blockIdx.x * BTILE;

    // ---------------- prologue: h0 = tanh(z @ z2h_w.T + b), k descending ----
    {
        float* zs = uni;                           // [k=128][b=16]
        for (int idx = tid; idx < BTILE * ZDIM; idx += NTHR) {
            int bi = idx >> 7, k = idx & 127;
            zs[k * 16 + bi] = z[(b0 + bi) * ZDIM + k];
        }
        if (tid < BTILE) tokS[tid] = 1;
        __syncthreads();
        for (int l = 0; l < 3; ++l) {
            const float* wr = z2h_w + (l * 256 + j) * ZDIM;
            float bias = z2h_b[l * 256 + j];
            u64 acc[NPAIR];
            #pragma unroll
            for (int p = 0; p < NPAIR; ++p) acc[p] = 0ull;
            for (int k = ZDIM - 1; k >= 0; --k) {
                u64 w2 = pack2dup(wr[k]);
                const float* zk = zs + k * 16;
                #pragma unroll
                for (int p = 0; p < NPAIR; ++p)
                    acc[p] = fma2(w2, *(const u64*)(zk + 2 * p), acc[p]);
            }
            float* hrow = hs + (l * 256 + j) * HS_STRIDE;
            #pragma unroll
            for (int p = 0; p < NPAIR; ++p) {
                float a, b; unpack2(acc[p], a, b);
                hrow[2 * p]     = xla_tanh(__fadd_rn(a, bias));
                hrow[2 * p + 1] = xla_tanh(__fadd_rn(b, bias));
            }
        }
        __syncthreads();
    }

    // biases (kept separate, rounded per-op in epilogue)
    const float bhr0 = b_hh0[j], bhz0 = b_hh0[256 + j], bhn0 = b_hh0[512 + j];
    const float bir1 = b_ih1[j], biz1 = b_ih1[256 + j], bin1 = b_ih1[512 + j];
    const float bhr1 = b_hh1[j], bhz1 = b_hh1[256 + j], bhn1 = b_hh1[512 + j];
    const float bir2 = b_ih2[j], biz2 = b_ih2[256 + j], bin2 = b_ih2[512 + j];
    const float bhr2 = b_hh2[j], bhz2 = b_hh2[256 + j], bhn2 = b_hh2[512 + j];
    const float ob   = out_b[tid & 63];

    float* hs0 = hs;
    float* hs1 = hs +     256 * HS_STRIDE;
    float* hs2 = hs + 2 * 256 * HS_STRIDE;
    const float4* Whh0 = (const float4*)(g_P);
    const float4* Wih1 = (const float4*)(g_P +     196608);
    const float4* Whh1 = (const float4*)(g_P + 2 * 196608);
    const float4* Wih2 = (const float4*)(g_P + 3 * 196608);
    const float4* Whh2 = (const float4*)(g_P + 4 * 196608);

    for (int t = 0; t < TSTEPS; ++t) {
        u64 gir[NPAIR], giz[NPAIR], gin[NPAIR];
        u64 dhr[NPAIR], dhz[NPAIR], dhn[NPAIR];

        // -------- layer 0: gi from table (bias included), gh chained --------
        #pragma unroll
        for (int p = 0; p < NPAIR; ++p) {
            int ta = tokS[2 * p], tb = tokS[2 * p + 1];
            const float* ga = g_G0 + ta * 768 + j;
            const float* gb = g_G0 + tb * 768 + j;
            gir[p] = pack2(ga[0],   gb[0]);
            giz[p] = pack2(ga[256], gb[256]);
            gin[p] = pack2(ga[512], gb[512]);
            dhr[p] = 0ull; dhz[p] = 0ull; dhn[p] = 0ull;
        }
        accum_phase(Whh0, hs0, j, dhr, dhz, dhn);
        __syncthreads();
        gru_epilogue(hs0 + j * HS_STRIDE, gir, giz, gin, dhr, dhz, dhn,
                     bhr0, bhz0, bhn0);
        __syncthreads();

        // -------- layer 1: separate i-chain and h-chain ---------------------
        #pragma unroll
        for (int p = 0; p < NPAIR; ++p) {
            gir[p] = 0ull; giz[p] = 0ull; gin[p] = 0ull;
            dhr[p] = 0ull; dhz[p] = 0ull; dhn[p] = 0ull;
        }
        accum_phase(Wih1, hs0, j, gir, giz, gin);
        accum_phase(Whh1, hs1, j, dhr, dhz, dhn);
        {
            u64 r2 = pack2dup(bir1), z2 = pack2dup(biz1), n2 = pack2dup(bin1);
            #pragma unroll
            for (int p = 0; p < NPAIR; ++p) {
                gir[p] = add2(gir[p], r2);
                giz[p] = add2(giz[p], z2);
                gin[p] = add2(gin[p], n2);
            }
        }
        __syncthreads();
        gru_epilogue(hs1 + j * HS_STRIDE, gir, giz, gin, dhr, dhz, dhn,
                     bhr1, bhz1, bhn1);
        __syncthreads();

        // -------- layer 2 ----------------------------------------------------
        #pragma unroll
        for (int p = 0; p < NPAIR; ++p) {
            gir[p] = 0ull; giz[p] = 0ull; gin[p] = 0ull;
            dhr[p] = 0ull; dhz[p] = 0ull; dhn[p] = 0ull;
        }
        accum_phase(Wih2, hs1, j, gir, giz, gin);
        accum_phase(Whh2, hs2, j, dhr, dhz, dhn);
        {
            u64 r2 = pack2dup(bir2), z2 = pack2dup(biz2), n2 = pack2dup(bin2);
            #pragma unroll
            for (int p = 0; p < NPAIR; ++p) {
                gir[p] = add2(gir[p], r2);
                giz[p] = add2(giz[p], z2);
                gin[p] = add2(gin[p], n2);
            }
        }
        __syncthreads();
        gru_epilogue(hs2 + j * HS_STRIDE, gir, giz, gin, dhr, dhz, dhn,
                     bhr2, bhz2, bhn2);
        __syncthreads();

        // -------- logits (k descending) + write + argmax ---------------------
        {
            int v = tid & 63, bg = tid >> 6;       // 4 groups of 4 elements
            u64 lacc[2];
            lacc[0] = 0ull; lacc[1] = 0ull;
            const float* xb = hs2 + bg * 4;
            const float4* wv = (const float4*)g_out4 + v;
            #pragma unroll 1
            for (int k4 = 63; k4 >= 0; --k4) {
                float4 w4 = __ldg(wv + k4 * 64);
                float wa[4] = {w4.x, w4.y, w4.z, w4.w};
                const float* xk = xb + (k4 * 4) * HS_STRIDE;
                #pragma unroll
                for (int c = 3; c >= 0; --c) {
                    u64 d = pack2dup(wa[c]);
                    const float* xr = xk + c * HS_STRIDE;
                    lacc[0] = fma2(d, *(const u64*)(xr),     lacc[0]);
                    lacc[1] = fma2(d, *(const u64*)(xr + 2), lacc[1]);
                }
            }
            float* ls = uni;                       // [16][65]
            float* obase = out + (size_t)(b0 + bg * 4) * (TSTEPS * VDIM)
                               + (size_t)t * VDIM + v;
            #pragma unroll
            for (int p = 0; p < 2; ++p) {
                float va, vb; unpack2(lacc[p], va, vb);
                va = __fadd_rn(va, ob);
                vb = __fadd_rn(vb, ob);
                int e0 = bg * 4 + 2 * p;
                ls[e0 * 65 + v]       = va;
                ls[(e0 + 1) * 65 + v] = vb;
                obase[(size_t)(2 * p)     * (TSTEPS * VDIM)] = va;
                obase[(size_t)(2 * p + 1) * (TSTEPS * VDIM)] = vb;
            }
        }
        __syncthreads();
        if (tid < BTILE) {                         // first-max argmax
            const float* row = uni + tid * 65;
            float best = row[0]; int bi = 0;
            for (int vv = 1; vv < 64; ++vv) {
                float x = row[vv];
                if (x > best) { best = x; bi = vv; }
            }
            tokS[tid] = bi;
        }
        __syncthreads();
    }
}

// ---------------------------------------------------------------------------
extern "C" void kernel_launch(void* const* d_in, const int* in_sizes, int n_in,
                              void* d_out, int out_size)
{
    const float* z     = (const float*)d_in[0];
    const float* emb   = (const float*)d_in[1];
    const float* z2h_w = (const float*)d_in[2];
    const float* z2h_b = (const float*)d_in[3];
    const float* out_w = (const float*)d_in[4];
    const float* out_b = (const float*)d_in[5];
    const float* w_ih0 = (const float*)d_in[6];
    const float* w_hh0 = (const float*)d_in[7];
    const float* b_ih0 = (const float*)d_in[8];
    const float* b_hh0 = (const float*)d_in[9];
    const float* w_ih1 = (const float*)d_in[10];
    const float* w_hh1 = (const float*)d_in[11];
    const float* b_ih1 = (const float*)d_in[12];
    const float* b_hh1 = (const float*)d_in[13];
    const float* w_ih2 = (const float*)d_in[14];
    const float* w_hh2 = (const float*)d_in[15];
    const float* b_ih2 = (const float*)d_in[16];
    const float* b_hh2 = (const float*)d_in[17];
    float* out = (float*)d_out;

    prep_kernel<<<4096, 256>>>(emb, w_ih0, b_ih0, w_hh0,
                               w_ih1, w_hh1, w_ih2, w_hh2, out_w);

    const int smem_bytes = (3 * 256 * HS_STRIDE + 2048 + BTILE) * 4 + 64;
    cudaFuncSetAttribute(decoder_kernel,
                         cudaFuncAttributeMaxDynamicSharedMemorySize, smem_bytes);
    decoder_kernel<<<NCTA, NTHR, smem_bytes>>>(z, z2h_w, z2h_b, out_b,
                                               b_hh0, b_ih1, b_hh1,
                                               b_ih2, b_hh2, out);
}

// round 10
// speedup vs baseline: 1.1833x; 1.1833x over previous
#include <cuda_runtime.h>
#include <cstdint>

// ---------------------------------------------------------------------------
// MolDecoder: 3-layer GRU autoregressive decoder, B=4096, H=256, V=64, T=120.
// PASSING numerics (round 9, rel_err 4.5e-7): descending-k fp32 FMA chains,
// split i/h dots, separate bias adds, contracted XLA tanh / tanh-form sigmoid.
// THIS ROUND: performance only — identical arithmetic graph per element.
//   BTILE 16->32 (NCTA 128 = single wave on 148 SMs)
//   NTHR 256->512 (256 neurons x 2 batch-halves) -> 16 warps/SM, occ 2x
//   biases moved to SMEM so 512 threads fit the register file
// ---------------------------------------------------------------------------

#define BATCH   4096
#define ZDIM    128
#define HDIM    256
#define VDIM    64
#define TSTEPS  119
#define BTILE   32
#define NPAIR   8                     // pairs per thread (half of 16)
#define NCTA    (BATCH / BTILE)       // 128
#define NTHR    512
#define HS_STRIDE 34                  // floats per h row (32 + 2 pad)

typedef unsigned long long u64;

// ---- packed f32x2 helpers (lane-wise IEEE fp32 ops) ------------------------
__device__ __forceinline__ u64 pack2(float lo, float hi) {
    u64 r; asm("mov.b64 %0, {%1, %2};" : "=l"(r) : "f"(lo), "f"(hi)); return r;
}
__device__ __forceinline__ u64 pack2dup(float w) {
    u64 r; asm("mov.b64 %0, {%1, %1};" : "=l"(r) : "f"(w)); return r;
}
__device__ __forceinline__ void unpack2(u64 v, float& lo, float& hi) {
    asm("mov.b64 {%0, %1}, %2;" : "=f"(lo), "=f"(hi) : "l"(v));
}
__device__ __forceinline__ u64 fma2(u64 a, u64 b, u64 c) {
    u64 r; asm("fma.rn.f32x2 %0, %1, %2, %3;" : "=l"(r) : "l"(a), "l"(b), "l"(c)); return r;
}
__device__ __forceinline__ u64 add2(u64 a, u64 b) {
    u64 r; asm("add.rn.f32x2 %0, %1, %2;" : "=l"(r) : "l"(a), "l"(b)); return r;
}

// ---- XLA activations, FMA-contracted (unchanged from passing round) --------
__device__ __forceinline__ float xla_tanh(float x) {
    float ax = fabsf(x);
    float xc = fminf(fmaxf(x, -9.0f), 9.0f);
    float x2 = __fmul_rn(xc, xc);
    float p = -2.76076847742355e-16f;
    p = __fmaf_rn(p, x2,  2.00018790482477e-13f);
    p = __fmaf_rn(p, x2, -8.60467152213735e-11f);
    p = __fmaf_rn(p, x2,  5.12229709037114e-08f);
    p = __fmaf_rn(p, x2,  1.48572235717979e-05f);
    p = __fmaf_rn(p, x2,  6.37261928875436e-04f);
    p = __fmaf_rn(p, x2,  4.89352455891786e-03f);
    p = __fmul_rn(xc, p);
    float q = 1.19825839466702e-06f;
    q = __fmaf_rn(q, x2, 1.18534705686654e-04f);
    q = __fmaf_rn(q, x2, 2.26843463243900e-03f);
    q = __fmaf_rn(q, x2, 4.89352518554385e-03f);
    float r = __fdiv_rn(p, q);
    return (ax < 0.0004f) ? x : r;
}
__device__ __forceinline__ float xla_sigmoid(float x) {
    float t = xla_tanh(__fmul_rn(0.5f, x));
    return __fmaf_rn(0.5f, t, 0.5f);
}

// ---- persistent device scratch ---------------------------------------------
__device__ float g_P[5 * 196608];           // 5 matrices, k4-interleaved
__device__ float g_G0[64 * 768];            // layer-0 gi table (incl b_ih0)
__device__ float g_out4[64 * 64 * 4];       // out_w packed [k4][v][c]

// ---------------------------------------------------------------------------
__global__ void prep_kernel(const float* __restrict__ emb,
                            const float* __restrict__ w_ih0,
                            const float* __restrict__ b_ih0,
                            const float* __restrict__ w_hh0,
                            const float* __restrict__ w_ih1,
                            const float* __restrict__ w_hh1,
                            const float* __restrict__ w_ih2,
                            const float* __restrict__ w_hh2,
                            const float* __restrict__ out_w)
{
    int idx = blockIdx.x * 256 + threadIdx.x;
    if (idx < 983040) {                        // pack 5 matrices
        int m = idx / 196608, r = idx % 196608;
        int f4i = r >> 2, c = r & 3;
        int k4 = f4i / 768, gj = f4i % 768;
        const float* src = (m == 0) ? w_hh0 : (m == 1) ? w_ih1 :
                           (m == 2) ? w_hh1 : (m == 3) ? w_ih2 : w_hh2;
        g_P[idx] = src[gj * 256 + 4 * k4 + c];
    } else if (idx < 1032192) {                // G0: fp32 DESCENDING chain + bias
        int i = idx - 983040;
        int v = i / 768, gj = i % 768;
        const float* wrow = w_ih0 + gj * 64;
        const float* e    = emb   + v  * 64;
        float c = 0.0f;
        for (int k = 63; k >= 0; --k) c = __fmaf_rn(wrow[k], e[k], c);
        g_G0[i] = __fadd_rn(c, b_ih0[gj]);
    } else if (idx < 1048576) {                // pack out_w [k4][v][c]
        int i = idx - 1032192;
        int f4i = i >> 2, c = i & 3;
        int k4 = f4i / 64, v = f4i % 64;
        g_out4[i] = out_w[v * 256 + 4 * k4 + c];
    }
}

// ---------------------------------------------------------------------------
// One matrix pass: 3 gates x 8 pairs, DESCENDING k = 255..0, single fp32
// accumulator per (gate, pair). xs already offset to this thread's batch half.
// ---------------------------------------------------------------------------
__device__ __forceinline__ void accum_phase(const float4* __restrict__ wbase,
                                            const float* __restrict__ xs,
                                            int j, u64* a0, u64* a1, u64* a2)
{
    #pragma unroll 1
    for (int k4 = 63; k4 >= 0; --k4) {
        const float4* wp = wbase + k4 * 768 + j;
        float4 w0 = __ldg(wp);
        float4 w1 = __ldg(wp + 256);
        float4 w2 = __ldg(wp + 512);
        const float* xk = xs + (k4 * 4) * HS_STRIDE;
        float wa0[4] = {w0.x, w0.y, w0.z, w0.w};
        float wa1[4] = {w1.x, w1.y, w1.z, w1.w};
        float wa2[4] = {w2.x, w2.y, w2.z, w2.w};
        #pragma unroll
        for (int c = 3; c >= 0; --c) {
            u64 d0 = pack2dup(wa0[c]);
            u64 d1 = pack2dup(wa1[c]);
            u64 d2 = pack2dup(wa2[c]);
            const float* xr = xk + c * HS_STRIDE;
            #pragma unroll
            for (int p = 0; p < NPAIR; ++p) {
                u64 x2 = *(const u64*)(xr + 2 * p);
                a0[p] = fma2(d0, x2, a0[p]);
                a1[p] = fma2(d1, x2, a1[p]);
                a2[p] = fma2(d2, x2, a2[p]);
            }
        }
    }
}

// GRU epilogue (contracted form, identical to passing round):
// r = sigmoid(gi_r + (dh_r + bh_r)) ; u likewise ; hn = dh_n + bh_n
// n = tanh(fma(r, hn, gi_n)) ; h' = fma(1-u, n, u*h)
__device__ __forceinline__ void gru_epilogue(float* hrow,
                                             const u64* gir, const u64* giz, const u64* gin,
                                             const u64* dhr, const u64* dhz, const u64* dhn,
                                             float bhr, float bhz, float bhn)
{
    #pragma unroll
    for (int p = 0; p < NPAIR; ++p) {
        float gr0, gr1, gz0, gz1, gn0, gn1;
        float hr0, hr1, hz0, hz1, hn0, hn1;
        unpack2(gir[p], gr0, gr1);
        unpack2(giz[p], gz0, gz1);
        unpack2(gin[p], gn0, gn1);
        unpack2(dhr[p], hr0, hr1);
        unpack2(dhz[p], hz0, hz1);
        unpack2(dhn[p], hn0, hn1);
        float h0o = hrow[2 * p], h1o = hrow[2 * p + 1];
        float r0 = xla_sigmoid(__fadd_rn(gr0, __fadd_rn(hr0, bhr)));
        float r1 = xla_sigmoid(__fadd_rn(gr1, __fadd_rn(hr1, bhr)));
        float u0 = xla_sigmoid(__fadd_rn(gz0, __fadd_rn(hz0, bhz)));
        float u1 = xla_sigmoid(__fadd_rn(gz1, __fadd_rn(hz1, bhz)));
        float hh0 = __fadd_rn(hn0, bhn), hh1 = __fadd_rn(hn1, bhn);
        float n0 = xla_tanh(__fmaf_rn(r0, hh0, gn0));
        float n1 = xla_tanh(__fmaf_rn(r1, hh1, gn1));
        hrow[2 * p]     = __fmaf_rn(__fsub_rn(1.0f, u0), n0, __fmul_rn(u0, h0o));
        hrow[2 * p + 1] = __fmaf_rn(__fsub_rn(1.0f, u1), n1, __fmul_rn(u1, h1o));
    }
}

// ---------------------------------------------------------------------------
__global__ void __launch_bounds__(NTHR, 1)
decoder_kernel(const float* __restrict__ z,
               const float* __restrict__ z2h_w,
               const float* __restrict__ z2h_b,
               const float* __restrict__ out_b,
               const float* __restrict__ b_hh0,
               const float* __restrict__ b_ih1,
               const float* __restrict__ b_hh1,
               const float* __restrict__ b_ih2,
               const float* __restrict__ b_hh2,
               float* __restrict__ out)
{
    extern __shared__ float sm[];
    float* hs     = sm;                               // [3][256][HS_STRIDE]
    float* uni    = sm + 3 * 256 * HS_STRIDE;         // zs[128][32] / ls[32][65]
    float* bias_s = uni + 4096;                       // [15][256]
    int*   tokS   = (int*)(bias_s + 15 * 256);        // [32]

    const int tid = threadIdx.x;
    const int j   = tid & 255;                        // neuron
    const int hb  = tid >> 8;                         // batch half (0/1)
    const int b0  = blockIdx.x * BTILE;

    // ---------------- prologue -----------------------------------------------
    {
        float* zs = uni;                              // [k=128][b=32]
        for (int idx = tid; idx < BTILE * ZDIM; idx += NTHR) {
            int bi = idx >> 7, k = idx & 127;
            zs[k * 32 + bi] = z[(b0 + bi) * ZDIM + k];
        }
        if (tid < 256) {                              // biases -> smem
            bias_s[0  * 256 + tid] = b_hh0[tid];
            bias_s[1  * 256 + tid] = b_hh0[256 + tid];
            bias_s[2  * 256 + tid] = b_hh0[512 + tid];
            bias_s[3  * 256 + tid] = b_ih1[tid];
            bias_s[4  * 256 + tid] = b_ih1[256 + tid];
            bias_s[5  * 256 + tid] = b_ih1[512 + tid];
            bias_s[6  * 256 + tid] = b_hh1[tid];
            bias_s[7  * 256 + tid] = b_hh1[256 + tid];
            bias_s[8  * 256 + tid] = b_hh1[512 + tid];
            bias_s[9  * 256 + tid] = b_ih2[tid];
            bias_s[10 * 256 + tid] = b_ih2[256 + tid];
            bias_s[11 * 256 + tid] = b_ih2[512 + tid];
            bias_s[12 * 256 + tid] = b_hh2[tid];
            bias_s[13 * 256 + tid] = b_hh2[256 + tid];
            bias_s[14 * 256 + tid] = b_hh2[512 + tid];
        }
        if (tid < BTILE) tokS[tid] = 1;
        __syncthreads();
        // h0 = tanh(z @ z2h_w.T + b), descending k (same math as passing round)
        const float* zs2 = uni;
        for (int l = 0; l < 3; ++l) {
            const float* wr = z2h_w + (l * 256 + j) * ZDIM;
            float bias = z2h_b[l * 256 + j];
            u64 acc[NPAIR];
            #pragma unroll
            for (int p = 0; p < NPAIR; ++p) acc[p] = 0ull;
            for (int k = ZDIM - 1; k >= 0; --k) {
                u64 w2 = pack2dup(wr[k]);
                const float* zk = zs2 + k * 32 + hb * 16;
                #pragma unroll
                for (int p = 0; p < NPAIR; ++p)
                    acc[p] = fma2(w2, *(const u64*)(zk + 2 * p), acc[p]);
            }
            float* hrow = hs + (l * 256 + j) * HS_STRIDE + hb * 16;
            #pragma unroll
            for (int p = 0; p < NPAIR; ++p) {
                float a, b; unpack2(acc[p], a, b);
                hrow[2 * p]     = xla_tanh(__fadd_rn(a, bias));
                hrow[2 * p + 1] = xla_tanh(__fadd_rn(b, bias));
            }
        }
        __syncthreads();
    }

    const float ob = out_b[tid & 63];

    float* hs0 = hs;
    float* hs1 = hs +     256 * HS_STRIDE;
    float* hs2 = hs + 2 * 256 * HS_STRIDE;
    const float4* Whh0 = (const float4*)(g_P);
    const float4* Wih1 = (const float4*)(g_P +     196608);
    const float4* Whh1 = (const float4*)(g_P + 2 * 196608);
    const float4* Wih2 = (const float4*)(g_P + 3 * 196608);
    const float4* Whh2 = (const float4*)(g_P + 4 * 196608);

    for (int t = 0; t < TSTEPS; ++t) {
        u64 gir[NPAIR], giz[NPAIR], gin[NPAIR];
        u64 dhr[NPAIR], dhz[NPAIR], dhn[NPAIR];

        // -------- layer 0: gi from table (bias included), gh chained --------
        #pragma unroll
        for (int p = 0; p < NPAIR; ++p) {
            int ta = tokS[hb * 16 + 2 * p], tb = tokS[hb * 16 + 2 * p + 1];
            const float* ga = g_G0 + ta * 768 + j;
            const float* gb = g_G0 + tb * 768 + j;
            gir[p] = pack2(ga[0],   gb[0]);
            giz[p] = pack2(ga[256], gb[256]);
            gin[p] = pack2(ga[512], gb[512]);
            dhr[p] = 0ull; dhz[p] = 0ull; dhn[p] = 0ull;
        }
        accum_phase(Whh0, hs0 + hb * 16, j, dhr, dhz, dhn);
        __syncthreads();
        gru_epilogue(hs0 + j * HS_STRIDE + hb * 16, gir, giz, gin, dhr, dhz, dhn,
                     bias_s[j], bias_s[256 + j], bias_s[512 + j]);
        __syncthreads();

        // -------- layer 1 ----------------------------------------------------
        #pragma unroll
        for (int p = 0; p < NPAIR; ++p) {
            gir[p] = 0ull; giz[p] = 0ull; gin[p] = 0ull;
            dhr[p] = 0ull; dhz[p] = 0ull; dhn[p] = 0ull;
        }
        accum_phase(Wih1, hs0 + hb * 16, j, gir, giz, gin);
        accum_phase(Whh1, hs1 + hb * 16, j, dhr, dhz, dhn);
        {
            u64 r2 = pack2dup(bias_s[3 * 256 + j]);
            u64 z2 = pack2dup(bias_s[4 * 256 + j]);
            u64 n2 = pack2dup(bias_s[5 * 256 + j]);
            #pragma unroll
            for (int p = 0; p < NPAIR; ++p) {
                gir[p] = add2(gir[p], r2);
                giz[p] = add2(giz[p], z2);
                gin[p] = add2(gin[p], n2);
            }
        }
        __syncthreads();
        gru_epilogue(hs1 + j * HS_STRIDE + hb * 16, gir, giz, gin, dhr, dhz, dhn,
                     bias_s[6 * 256 + j], bias_s[7 * 256 + j], bias_s[8 * 256 + j]);
        __syncthreads();

        // -------- layer 2 ----------------------------------------------------
        #pragma unroll
        for (int p = 0; p < NPAIR; ++p) {
            gir[p] = 0ull; giz[p] = 0ull; gin[p] = 0ull;
            dhr[p] = 0ull; dhz[p] = 0ull; dhn[p] = 0ull;
        }
        accum_phase(Wih2, hs1 + hb * 16, j, gir, giz, gin);
        accum_phase(Whh2, hs2 + hb * 16, j, dhr, dhz, dhn);
        {
            u64 r2 = pack2dup(bias_s[9  * 256 + j]);
            u64 z2 = pack2dup(bias_s[10 * 256 + j]);
            u64 n2 = pack2dup(bias_s[11 * 256 + j]);
            #pragma unroll
            for (int p = 0; p < NPAIR; ++p) {
                gir[p] = add2(gir[p], r2);
                giz[p] = add2(giz[p], z2);
                gin[p] = add2(gin[p], n2);
            }
        }
        __syncthreads();
        gru_epilogue(hs2 + j * HS_STRIDE + hb * 16, gir, giz, gin, dhr, dhz, dhn,
                     bias_s[12 * 256 + j], bias_s[13 * 256 + j], bias_s[14 * 256 + j]);
        __syncthreads();

        // -------- logits (k descending) + write + argmax ---------------------
        {
            int v = tid & 63, bg = tid >> 6;       // 8 groups of 4 elements
            u64 lacc[2];
            lacc[0] = 0ull; lacc[1] = 0ull;
            const float* xb = hs2 + bg * 4;
            const float4* wv = (const float4*)g_out4 + v;
            #pragma unroll 1
            for (int k4 = 63; k4 >= 0; --k4) {
                float4 w4 = __ldg(wv + k4 * 64);
                float wa[4] = {w4.x, w4.y, w4.z, w4.w};
                const float* xk = xb + (k4 * 4) * HS_STRIDE;
                #pragma unroll
                for (int c = 3; c >= 0; --c) {
                    u64 d = pack2dup(wa[c]);
                    const float* xr = xk + c * HS_STRIDE;
                    lacc[0] = fma2(d, *(const u64*)(xr),     lacc[0]);
                    lacc[1] = fma2(d, *(const u64*)(xr + 2), lacc[1]);
                }
            }
            float* ls = uni;                       // [32][65]
            float* obase = out + (size_t)(b0 + bg * 4) * (TSTEPS * VDIM)
                               + (size_t)t * VDIM + v;
            #pragma unroll
            for (int p = 0; p < 2; ++p) {
                float va, vb; unpack2(lacc[p], va, vb);
                va = __fadd_rn(va, ob);
                vb = __fadd_rn(vb, ob);
                int e0 = bg * 4 + 2 * p;
                ls[e0 * 65 + v]       = va;
                ls[(e0 + 1) * 65 + v] = vb;
                obase[(size_t)(2 * p)     * (TSTEPS * VDIM)] = va;
                obase[(size_t)(2 * p + 1) * (TSTEPS * VDIM)] = vb;
            }
        }
        __syncthreads();
        if (tid < BTILE) {                         // first-max argmax
            const float* row = uni + tid * 65;
            float best = row[0]; int bi = 0;
            for (int vv = 1; vv < 64; ++vv) {
                float x = row[vv];
                if (x > best) { best = x; bi = vv; }
            }
            tokS[tid] = bi;
        }
        __syncthreads();
    }
}

// ---------------------------------------------------------------------------
extern "C" void kernel_launch(void* const* d_in, const int* in_sizes, int n_in,
                              void* d_out, int out_size)
{
    const float* z     = (const float*)d_in[0];
    const float* emb   = (const float*)d_in[1];
    const float* z2h_w = (const float*)d_in[2];
    const float* z2h_b = (const float*)d_in[3];
    const float* out_w = (const float*)d_in[4];
    const float* out_b = (const float*)d_in[5];
    const float* w_ih0 = (const float*)d_in[6];
    const float* w_hh0 = (const float*)d_in[7];
    const float* b_ih0 = (const float*)d_in[8];
    const float* b_hh0 = (const float*)d_in[9];
    const float* w_ih1 = (const float*)d_in[10];
    const float* w_hh1 = (const float*)d_in[11];
    const float* b_ih1 = (const float*)d_in[12];
    const float* b_hh1 = (const float*)d_in[13];
    const float* w_ih2 = (const float*)d_in[14];
    const float* w_hh2 = (const float*)d_in[15];
    const float* b_ih2 = (const float*)d_in[16];
    const float* b_hh2 = (const float*)d_in[17];
    float* out = (float*)d_out;

    prep_kernel<<<4096, 256>>>(emb, w_ih0, b_ih0, w_hh0,
                               w_ih1, w_hh1, w_ih2, w_hh2, out_w);

    const int smem_bytes =
        (3 * 256 * HS_STRIDE + 4096 + 15 * 256 + BTILE) * 4 + 64;
    cudaFuncSetAttribute(decoder_kernel,
                         cudaFuncAttributeMaxDynamicSharedMemorySize, smem_bytes);
    decoder_kernel<<<NCTA, NTHR, smem_bytes>>>(z, z2h_w, z2h_b, out_b,
                                               b_hh0, b_ih1, b_hh1,
                                               b_ih2, b_hh2, out);
}

// round 11
// speedup vs baseline: 1.2453x; 1.0524x over previous
#include <cuda_runtime.h>
#include <cstdint>

// ---------------------------------------------------------------------------
// MolDecoder: 3-layer GRU autoregressive decoder, B=4096, H=256, V=64, T=120.
// PASSING numerics (rel_err 4.5e-7): descending-k fp32 FMA chains, split i/h
// dots, separate bias adds, contracted XLA tanh / tanh-form sigmoid.
// R11 performance changes (arithmetic-preserving):
//   - LDS.128 x-loads (HS_STRIDE 36)
//   - manual prefetch double-buffer on weight LDG.128
//   - layer-0 gi loaded in epilogue; layer-1/2 i-chains staged to SMEM scratch
//     -> live accum regs halved, no spills at 512 threads
// ---------------------------------------------------------------------------

#define BATCH   4096
#define ZDIM    128
#define HDIM    256
#define VDIM    64
#define TSTEPS  119
#define BTILE   32
#define NPAIR   8                     // pairs per thread (16 elems / 2)
#define NCTA    (BATCH / BTILE)       // 128
#define NTHR    512
#define HS_STRIDE 36                  // floats per h row (32 + 4 pad, 16B-mult)

typedef unsigned long long u64;

// ---- packed f32x2 helpers (lane-wise IEEE fp32 ops) ------------------------
__device__ __forceinline__ u64 pack2(float lo, float hi) {
    u64 r; asm("mov.b64 %0, {%1, %2};" : "=l"(r) : "f"(lo), "f"(hi)); return r;
}
__device__ __forceinline__ u64 pack2dup(float w) {
    u64 r; asm("mov.b64 %0, {%1, %1};" : "=l"(r) : "f"(w)); return r;
}
__device__ __forceinline__ void unpack2(u64 v, float& lo, float& hi) {
    asm("mov.b64 {%0, %1}, %2;" : "=f"(lo), "=f"(hi) : "l"(v));
}
__device__ __forceinline__ u64 fma2(u64 a, u64 b, u64 c) {
    u64 r; asm("fma.rn.f32x2 %0, %1, %2, %3;" : "=l"(r) : "l"(a), "l"(b), "l"(c)); return r;
}

// ---- XLA activations, FMA-contracted (unchanged) ----------------------------
__device__ __forceinline__ float xla_tanh(float x) {
    float ax = fabsf(x);
    float xc = fminf(fmaxf(x, -9.0f), 9.0f);
    float x2 = __fmul_rn(xc, xc);
    float p = -2.76076847742355e-16f;
    p = __fmaf_rn(p, x2,  2.00018790482477e-13f);
    p = __fmaf_rn(p, x2, -8.60467152213735e-11f);
    p = __fmaf_rn(p, x2,  5.12229709037114e-08f);
    p = __fmaf_rn(p, x2,  1.48572235717979e-05f);
    p = __fmaf_rn(p, x2,  6.37261928875436e-04f);
    p = __fmaf_rn(p, x2,  4.89352455891786e-03f);
    p = __fmul_rn(xc, p);
    float q = 1.19825839466702e-06f;
    q = __fmaf_rn(q, x2, 1.18534705686654e-04f);
    q = __fmaf_rn(q, x2, 2.26843463243900e-03f);
    q = __fmaf_rn(q, x2, 4.89352518554385e-03f);
    float r = __fdiv_rn(p, q);
    return (ax < 0.0004f) ? x : r;
}
__device__ __forceinline__ float xla_sigmoid(float x) {
    float t = xla_tanh(__fmul_rn(0.5f, x));
    return __fmaf_rn(0.5f, t, 0.5f);
}

// ---- persistent device scratch ---------------------------------------------
__device__ float g_P[5 * 196608];           // 5 matrices, k4-interleaved
__device__ float g_G0[64 * 768];            // layer-0 gi table (incl b_ih0)
__device__ float g_out4[64 * 64 * 4];       // out_w packed [k4][v][c]

// ---------------------------------------------------------------------------
__global__ void prep_kernel(const float* __restrict__ emb,
                            const float* __restrict__ w_ih0,
                            const float* __restrict__ b_ih0,
                            const float* __restrict__ w_hh0,
                            const float* __restrict__ w_ih1,
                            const float* __restrict__ w_hh1,
                            const float* __restrict__ w_ih2,
                            const float* __restrict__ w_hh2,
                            const float* __restrict__ out_w)
{
    int idx = blockIdx.x * 256 + threadIdx.x;
    if (idx < 983040) {                        // pack 5 matrices
        int m = idx / 196608, r = idx % 196608;
        int f4i = r >> 2, c = r & 3;
        int k4 = f4i / 768, gj = f4i % 768;
        const float* src = (m == 0) ? w_hh0 : (m == 1) ? w_ih1 :
                           (m == 2) ? w_hh1 : (m == 3) ? w_ih2 : w_hh2;
        g_P[idx] = src[gj * 256 + 4 * k4 + c];
    } else if (idx < 1032192) {                // G0: fp32 DESCENDING chain + bias
        int i = idx - 983040;
        int v = i / 768, gj = i % 768;
        const float* wrow = w_ih0 + gj * 64;
        const float* e    = emb   + v  * 64;
        float c = 0.0f;
        for (int k = 63; k >= 0; --k) c = __fmaf_rn(wrow[k], e[k], c);
        g_G0[i] = __fadd_rn(c, b_ih0[gj]);
    } else if (idx < 1048576) {                // pack out_w [k4][v][c]
        int i = idx - 1032192;
        int f4i = i >> 2, c = i & 3;
        int k4 = f4i / 64, v = f4i % 64;
        g_out4[i] = out_w[v * 256 + 4 * k4 + c];
    }
}

// ---------------------------------------------------------------------------
// One matrix pass: 3 gates x 8 pairs, DESCENDING k = 255..0, single fp32
// accumulator per (gate, pair). Weight LDG.128 double-buffered one k4 ahead.
// x loaded as LDS.128 (ulonglong2). Arithmetic order identical to R9/R10.
// ---------------------------------------------------------------------------
__device__ __forceinline__ void accum_phase(const float4* __restrict__ wbase,
                                            const float* __restrict__ xs,
                                            int j, u64* a0, u64* a1, u64* a2)
{
    const float4* wp = wbase + 63 * 768 + j;
    float4 n0 = __ldg(wp);
    float4 n1 = __ldg(wp + 256);
    float4 n2 = __ldg(wp + 512);
    #pragma unroll 1
    for (int k4 = 63; k4 >= 0; --k4) {
        float4 c0 = n0, c1 = n1, c2 = n2;
        if (k4 > 0) {
            const float4* np = wbase + (k4 - 1) * 768 + j;
            n0 = __ldg(np);
            n1 = __ldg(np + 256);
            n2 = __ldg(np + 512);
        }
        const float* xk = xs + (k4 * 4) * HS_STRIDE;
        float wa0[4] = {c0.x, c0.y, c0.z, c0.w};
        float wa1[4] = {c1.x, c1.y, c1.z, c1.w};
        float wa2[4] = {c2.x, c2.y, c2.z, c2.w};
        #pragma unroll
        for (int c = 3; c >= 0; --c) {
            u64 d0 = pack2dup(wa0[c]);
            u64 d1 = pack2dup(wa1[c]);
            u64 d2 = pack2dup(wa2[c]);
            const float* xr = xk + c * HS_STRIDE;
            ulonglong2 xa = *(const ulonglong2*)(xr);
            ulonglong2 xb = *(const ulonglong2*)(xr + 4);
            ulonglong2 xc = *(const ulonglong2*)(xr + 8);
            ulonglong2 xd = *(const ulonglong2*)(xr + 12);
            u64 xv[NPAIR] = {xa.x, xa.y, xb.x, xb.y, xc.x, xc.y, xd.x, xd.y};
            #pragma unroll
            for (int p = 0; p < NPAIR; ++p) {
                a0[p] = fma2(d0, xv[p], a0[p]);
                a1[p] = fma2(d1, xv[p], a1[p]);
                a2[p] = fma2(d2, xv[p], a2[p]);
            }
        }
    }
}

// Gate math for one batch pair (identical ops/order to passing rounds):
// r = sigmoid(gr + (hr + bhr)) ; u likewise ; hn = dhn + bhn
// n = tanh(fma(r, hn, gn)) ; h' = fma(1-u, n, u*h)
__device__ __forceinline__ void gates_pair(float* hrow, int p,
                                           float gr0, float gr1,
                                           float gz0, float gz1,
                                           float gn0, float gn1,
                                           u64 dr, u64 dz, u64 dn,
                                           float bhr, float bhz, float bhn)
{
    float hr0, hr1, hz0, hz1, hn0, hn1;
    unpack2(dr, hr0, hr1);
    unpack2(dz, hz0, hz1);
    unpack2(dn, hn0, hn1);
    float h0o = hrow[2 * p], h1o = hrow[2 * p + 1];
    float r0 = xla_sigmoid(__fadd_rn(gr0, __fadd_rn(hr0, bhr)));
    float r1 = xla_sigmoid(__fadd_rn(gr1, __fadd_rn(hr1, bhr)));
    float u0 = xla_sigmoid(__fadd_rn(gz0, __fadd_rn(hz0, bhz)));
    float u1 = xla_sigmoid(__fadd_rn(gz1, __fadd_rn(hz1, bhz)));
    float hh0 = __fadd_rn(hn0, bhn), hh1 = __fadd_rn(hn1, bhn);
    float n0 = xla_tanh(__fmaf_rn(r0, hh0, gn0));
    float n1 = xla_tanh(__fmaf_rn(r1, hh1, gn1));
    hrow[2 * p]     = __fmaf_rn(__fsub_rn(1.0f, u0), n0, __fmul_rn(u0, h0o));
    hrow[2 * p + 1] = __fmaf_rn(__fsub_rn(1.0f, u1), n1, __fmul_rn(u1, h1o));
}

// ---------------------------------------------------------------------------
__global__ void __launch_bounds__(NTHR, 1)
decoder_kernel(const float* __restrict__ z,
               const float* __restrict__ z2h_w,
               const float* __restrict__ z2h_b,
               const float* __restrict__ out_b,
               const float* __restrict__ b_hh0,
               const float* __restrict__ b_ih1,
               const float* __restrict__ b_hh1,
               const float* __restrict__ b_ih2,
               const float* __restrict__ b_hh2,
               float* __restrict__ out)
{
    extern __shared__ float sm[];
    float* hs     = sm;                               // [3][256][36] = 27648
    float* uni    = sm + 3 * 256 * HS_STRIDE;         // 24576: zs / scr / ls
    float* bias_s = uni + 24576;                      // [15][256]
    int*   tokS   = (int*)(bias_s + 15 * 256);        // [32]
    u64*   scr    = (u64*)uni;                        // [24][512] u64 scratch

    const int tid = threadIdx.x;
    const int j   = tid & 255;                        // neuron
    const int hb  = tid >> 8;                         // batch half (0/1)
    const int b0  = blockIdx.x * BTILE;

    // ---------------- prologue -----------------------------------------------
    {
        float* zs = uni;                              // [k=128][b=32]
        for (int idx = tid; idx < BTILE * ZDIM; idx += NTHR) {
            int bi = idx >> 7, k = idx & 127;
            zs[k * 32 + bi] = z[(b0 + bi) * ZDIM + k];
        }
        if (tid < 256) {                              // biases -> smem
            bias_s[0  * 256 + tid] = b_hh0[tid];
            bias_s[1  * 256 + tid] = b_hh0[256 + tid];
            bias_s[2  * 256 + tid] = b_hh0[512 + tid];
            bias_s[3  * 256 + tid] = b_ih1[tid];
            bias_s[4  * 256 + tid] = b_ih1[256 + tid];
            bias_s[5  * 256 + tid] = b_ih1[512 + tid];
            bias_s[6  * 256 + tid] = b_hh1[tid];
            bias_s[7  * 256 + tid] = b_hh1[256 + tid];
            bias_s[8  * 256 + tid] = b_hh1[512 + tid];
            bias_s[9  * 256 + tid] = b_ih2[tid];
            bias_s[10 * 256 + tid] = b_ih2[256 + tid];
            bias_s[11 * 256 + tid] = b_ih2[512 + tid];
            bias_s[12 * 256 + tid] = b_hh2[tid];
            bias_s[13 * 256 + tid] = b_hh2[256 + tid];
            bias_s[14 * 256 + tid] = b_hh2[512 + tid];
        }
        if (tid < BTILE) tokS[tid] = 1;
        __syncthreads();
        // h0 = tanh(z @ z2h_w.T + b), descending k (same math as passing round)
        const float* zs2 = uni;
        for (int l = 0; l < 3; ++l) {
            const float* wr = z2h_w + (l * 256 + j) * ZDIM;
            float bias = z2h_b[l * 256 + j];
            u64 acc[NPAIR];
            #pragma unroll
            for (int p = 0; p < NPAIR; ++p) acc[p] = 0ull;
            for (int k = ZDIM - 1; k >= 0; --k) {
                u64 w2 = pack2dup(wr[k]);
                const float* zk = zs2 + k * 32 + hb * 16;
                #pragma unroll
                for (int p = 0; p < NPAIR; ++p)
                    acc[p] = fma2(w2, *(const u64*)(zk + 2 * p), acc[p]);
            }
            float* hrow = hs + (l * 256 + j) * HS_STRIDE + hb * 16;
            #pragma unroll
            for (int p = 0; p < NPAIR; ++p) {
                float a, b; unpack2(acc[p], a, b);
                hrow[2 * p]     = xla_tanh(__fadd_rn(a, bias));
                hrow[2 * p + 1] = xla_tanh(__fadd_rn(b, bias));
            }
        }
        __syncthreads();
    }

    const float ob = out_b[tid & 63];

    float* hs0 = hs;
    float* hs1 = hs +     256 * HS_STRIDE;
    float* hs2 = hs + 2 * 256 * HS_STRIDE;
    const float4* Whh0 = (const float4*)(g_P);
    const float4* Wih1 = (const float4*)(g_P +     196608);
    const float4* Whh1 = (const float4*)(g_P + 2 * 196608);
    const float4* Wih2 = (const float4*)(g_P + 3 * 196608);
    const float4* Whh2 = (const float4*)(g_P + 4 * 196608);

    u64 acc0[NPAIR], acc1[NPAIR], acc2[NPAIR];

    for (int t = 0; t < TSTEPS; ++t) {
        // -------- layer 0: dh chains; gi loaded from G0 in epilogue ----------
        #pragma unroll
        for (int p = 0; p < NPAIR; ++p) { acc0[p] = 0; acc1[p] = 0; acc2[p] = 0; }
        accum_phase(Whh0, hs0 + hb * 16, j, acc0, acc1, acc2);
        __syncthreads();
        {
            float* hrow = hs0 + j * HS_STRIDE + hb * 16;
            float bhr = bias_s[j], bhz = bias_s[256 + j], bhn = bias_s[512 + j];
            #pragma unroll
            for (int p = 0; p < NPAIR; ++p) {
                int ta = tokS[hb * 16 + 2 * p], tb = tokS[hb * 16 + 2 * p + 1];
                const float* ga = g_G0 + ta * 768 + j;
                const float* gb = g_G0 + tb * 768 + j;
                gates_pair(hrow, p, ga[0], gb[0], ga[256], gb[256],
                           ga[512], gb[512], acc0[p], acc1[p], acc2[p],
                           bhr, bhz, bhn);
            }
        }
        __syncthreads();

        // -------- layer 1: i-chains -> scratch, then h-chains ----------------
        #pragma unroll
        for (int p = 0; p < NPAIR; ++p) { acc0[p] = 0; acc1[p] = 0; acc2[p] = 0; }
        accum_phase(Wih1, hs0 + hb * 16, j, acc0, acc1, acc2);
        #pragma unroll
        for (int p = 0; p < NPAIR; ++p) {
            scr[(0 * 8 + p) * NTHR + tid]  = acc0[p];
            scr[(1 * 8 + p) * NTHR + tid]  = acc1[p];
            scr[(2 * 8 + p) * NTHR + tid]  = acc2[p];
        }
        #pragma unroll
        for (int p = 0; p < NPAIR; ++p) { acc0[p] = 0; acc1[p] = 0; acc2[p] = 0; }
        accum_phase(Whh1, hs1 + hb * 16, j, acc0, acc1, acc2);
        __syncthreads();
        {
            float* hrow = hs1 + j * HS_STRIDE + hb * 16;
            float bir = bias_s[3 * 256 + j], biz = bias_s[4 * 256 + j],
                  bin = bias_s[5 * 256 + j];
            float bhr = bias_s[6 * 256 + j], bhz = bias_s[7 * 256 + j],
                  bhn = bias_s[8 * 256 + j];
            #pragma unroll
            for (int p = 0; p < NPAIR; ++p) {
                float gr0, gr1, gz0, gz1, gn0, gn1;
                unpack2(scr[(0 * 8 + p) * NTHR + tid], gr0, gr1);
                unpack2(scr[(1 * 8 + p) * NTHR + tid], gz0, gz1);
                unpack2(scr[(2 * 8 + p) * NTHR + tid], gn0, gn1);
                gates_pair(hrow, p,
                           __fadd_rn(gr0, bir), __fadd_rn(gr1, bir),
                           __fadd_rn(gz0, biz), __fadd_rn(gz1, biz),
                           __fadd_rn(gn0, bin), __fadd_rn(gn1, bin),
                           acc0[p], acc1[p], acc2[p], bhr, bhz, bhn);
            }
        }
        __syncthreads();

        // -------- layer 2 ----------------------------------------------------
        #pragma unroll
        for (int p = 0; p < NPAIR; ++p) { acc0[p] = 0; acc1[p] = 0; acc2[p] = 0; }
        accum_phase(Wih2, hs1 + hb * 16, j, acc0, acc1, acc2);
        #pragma unroll
        for (int p = 0; p < NPAIR; ++p) {
            scr[(0 * 8 + p) * NTHR + tid]  = acc0[p];
            scr[(1 * 8 + p) * NTHR + tid]  = acc1[p];
            scr[(2 * 8 + p) * NTHR + tid]  = acc2[p];
        }
        #pragma unroll
        for (int p = 0; p < NPAIR; ++p) { acc0[p] = 0; acc1[p] = 0; acc2[p] = 0; }
        accum_phase(Whh2, hs2 + hb * 16, j, acc0, acc1, acc2);
        __syncthreads();
        {
            float* hrow = hs2 + j * HS_STRIDE + hb * 16;
            float bir = bias_s[9  * 256 + j], biz = bias_s[10 * 256 + j],
                  bin = bias_s[11 * 256 + j];
            float bhr = bias_s[12 * 256 + j], bhz = bias_s[13 * 256 + j],
                  bhn = bias_s[14 * 256 + j];
            #pragma unroll
            for (int p = 0; p < NPAIR; ++p) {
                float gr0, gr1, gz0, gz1, gn0, gn1;
                unpack2(scr[(0 * 8 + p) * NTHR + tid], gr0, gr1);
                unpack2(scr[(1 * 8 + p) * NTHR + tid], gz0, gz1);
                unpack2(scr[(2 * 8 + p) * NTHR + tid], gn0, gn1);
                gates_pair(hrow, p,
                           __fadd_rn(gr0, bir), __fadd_rn(gr1, bir),
                           __fadd_rn(gz0, biz), __fadd_rn(gz1, biz),
                           __fadd_rn(gn0, bin), __fadd_rn(gn1, bin),
                           acc0[p], acc1[p], acc2[p], bhr, bhz, bhn);
            }
        }
        __syncthreads();

        // -------- logits (k descending, prefetched) + write + argmax ---------
        {
            int v = tid & 63, bg = tid >> 6;       // 8 groups of 4 elements
            u64 lacc[2];
            lacc[0] = 0ull; lacc[1] = 0ull;
            const float* xb = hs2 + bg * 4;
            const float4* wv = (const float4*)g_out4 + v;
            float4 nw = __ldg(wv + 63 * 64);
            #pragma unroll 1
            for (int k4 = 63; k4 >= 0; --k4) {
                float4 cw = nw;
                if (k4 > 0) nw = __ldg(wv + (k4 - 1) * 64);
                float wa[4] = {cw.x, cw.y, cw.z, cw.w};
                #pragma unroll
                for (int c = 3; c >= 0; --c) {
                    u64 d = pack2dup(wa[c]);
                    const float* xr = xb + (k4 * 4 + c) * HS_STRIDE;
                    ulonglong2 xx = *(const ulonglong2*)(xr);
                    lacc[0] = fma2(d, xx.x, lacc[0]);
                    lacc[1] = fma2(d, xx.y, lacc[1]);
                }
            }
            float* ls = uni;                       // [32][65]
            float* obase = out + (size_t)(b0 + bg * 4) * (TSTEPS * VDIM)
                               + (size_t)t * VDIM + v;
            #pragma unroll
            for (int p = 0; p < 2; ++p) {
                float va, vb; unpack2(lacc[p], va, vb);
                va = __fadd_rn(va, ob);
                vb = __fadd_rn(vb, ob);
                int e0 = bg * 4 + 2 * p;
                ls[e0 * 65 + v]       = va;
                ls[(e0 + 1) * 65 + v] = vb;
                obase[(size_t)(2 * p)     * (TSTEPS * VDIM)] = va;
                obase[(size_t)(2 * p + 1) * (TSTEPS * VDIM)] = vb;
            }
        }
        __syncthreads();
        if (tid < BTILE) {                         // first-max argmax
            const float* row = uni + tid * 65;
            float best = row[0]; int bi = 0;
            for (int vv = 1; vv < 64; ++vv) {
                float x = row[vv];
                if (x > best) { best = x; bi = vv; }
            }
            tokS[tid] = bi;
        }
        __syncthreads();
    }
}

// ---------------------------------------------------------------------------
extern "C" void kernel_launch(void* const* d_in, const int* in_sizes, int n_in,
                              void* d_out, int out_size)
{
    const float* z     = (const float*)d_in[0];
    const float* emb   = (const float*)d_in[1];
    const float* z2h_w = (const float*)d_in[2];
    const float* z2h_b = (const float*)d_in[3];
    const float* out_w = (const float*)d_in[4];
    const float* out_b = (const float*)d_in[5];
    const float* w_ih0 = (const float*)d_in[6];
    const float* w_hh0 = (const float*)d_in[7];
    const float* b_ih0 = (const float*)d_in[8];
    const float* b_hh0 = (const float*)d_in[9];
    const float* w_ih1 = (const float*)d_in[10];
    const float* w_hh1 = (const float*)d_in[11];
    const float* b_ih1 = (const float*)d_in[12];
    const float* b_hh1 = (const float*)d_in[13];
    const float* w_ih2 = (const float*)d_in[14];
    const float* w_hh2 = (const float*)d_in[15];
    const float* b_ih2 = (const float*)d_in[16];
    const float* b_hh2 = (const float*)d_in[17];
    float* out = (float*)d_out;

    prep_kernel<<<4096, 256>>>(emb, w_ih0, b_ih0, w_hh0,
                               w_ih1, w_hh1, w_ih2, w_hh2, out_w);

    const int smem_bytes =
        (3 * 256 * HS_STRIDE + 24576 + 15 * 256 + BTILE) * 4;  // 224384
    cudaFuncSetAttribute(decoder_kernel,
                         cudaFuncAttributeMaxDynamicSharedMemorySize, smem_bytes);
    decoder_kernel<<<NCTA, NTHR, smem_bytes>>>(z, z2h_w, z2h_b, out_b,
                                               b_hh0, b_ih1, b_hh1,
                                               b_ih2, b_hh2, out);
}